// round 12
// baseline (speedup 1.0000x reference)
#include <cuda_runtime.h>

#define Bc 4
#define Nc 8192
#define NPc 2048
#define NSc 32
#define CINc 128
#define COUTc 256

// Scratch (no cudaMalloc allowed): device globals
__device__ int   g_fidx[Bc * NPc];
__device__ float g_featsT[(size_t)Bc * Nc * CINc];    // [B, N, CIN]  16 MB
__device__ float g_pooledT[(size_t)Bc * NPc * CINc];  // [B, NP, CIN]  4 MB

// ---------------- packed f32x2 helpers (sm_103a) ----------------
// NOTE: only add/mul/fma exist in f32x2 form; min/max do NOT (ptxas rejects).
typedef unsigned long long ull;

__device__ __forceinline__ ull f2pack(float lo, float hi) {
    ull r; asm("mov.b64 %0, {%1, %2};" : "=l"(r) : "f"(lo), "f"(hi)); return r;
}
__device__ __forceinline__ float2 f2unpack(ull v) {
    float2 f; asm("mov.b64 {%0, %1}, %2;" : "=f"(f.x), "=f"(f.y) : "l"(v)); return f;
}
__device__ __forceinline__ ull f2add(ull a, ull b) {
    ull r; asm("add.rn.f32x2 %0, %1, %2;" : "=l"(r) : "l"(a), "l"(b)); return r;
}
__device__ __forceinline__ ull f2mul(ull a, ull b) {
    ull r; asm("mul.rn.f32x2 %0, %1, %2;" : "=l"(r) : "l"(a), "l"(b)); return r;
}
__device__ __forceinline__ ull f2fma(ull a, ull b, ull c) {
    ull r; asm("fma.rn.f32x2 %0, %1, %2, %3;" : "=l"(r) : "l"(a), "l"(b), "l"(c)); return r;
}

__device__ __forceinline__ unsigned expand6(unsigned v) {  // 6 bits -> every 3rd bit
    v = (v * 0x00010001u) & 0xFF0000FFu;
    v = (v * 0x00000101u) & 0x0F00F00Fu;
    v = (v * 0x00000011u) & 0xC30C30C3u;
    v = (v * 0x00000005u) & 0x49249249u;
    return v;
}

// ---------------------------------------------------------------------------
// 1) Furthest point sampling. 1024 threads/block (one block per batch),
//    8 Morton-contiguous points/thread (bitonic-sorted in shared).
//    Rationale: with exact bounding-sphere pruning + cached candc, per-thread
//    issue is tiny, so more/thinner threads shrink the WINNER warp's serial
//    path (update 4 packed groups, candc scan 8, tighter spheres) which is
//    the binding constraint.
//    Per iteration (one __syncthreads):
//      stage 1: REDUX.MAX on value bits; lanes with bv==best atomicMin their
//      cached candc into a PER-WARP slot (distinct addresses, no cross-warp
//      serialization) -> (value, min-original-index) pair per warp.
//      stage 2: lane reads warp 'lane''s pair (32 pairs), REDUX.MAX/REDUX.MIN.
//    si[] triple-buffered; at iter k lane0 resets slot (k+1)%3 (2 barriers of
//    separation each side -> race-free).
//    candc + squared prune threshold cached, recomputed only in the update
//    branch. Tie-break = lowest original index, exact.
// ---------------------------------------------------------------------------
__global__ void __launch_bounds__(1024, 1) fps_kernel(const float* __restrict__ xyz) {
    const int b = blockIdx.x;
    const float* xb = xyz + (size_t)b * Nc * 3;
    const int t = threadIdx.x;
    const int lane = t & 31;
    const int wid = t >> 5;

    __shared__ unsigned skey[Nc];        // 32 KB: (morton18 << 13) | idx13
    __shared__ unsigned sv[3][32];
    __shared__ int      si[3][32];

    // ---- phase A: build sort keys ----
#pragma unroll
    for (int r = 0; r < 8; r++) {
        const int i = t + r * 1024;
        const float x = xb[3 * i], y = xb[3 * i + 1], z = xb[3 * i + 2];
        unsigned cx = min(63u, (unsigned)(x * 64.0f));
        unsigned cy = min(63u, (unsigned)(y * 64.0f));
        unsigned cz = min(63u, (unsigned)(z * 64.0f));
        const unsigned m = (expand6(cz) << 2) | (expand6(cy) << 1) | expand6(cx);
        skey[i] = (m << 13) | (unsigned)i;
    }
    __syncthreads();

    // ---- phase B: bitonic sort (8192 u32) ----
    for (unsigned ksz = 2; ksz <= (unsigned)Nc; ksz <<= 1) {
        for (unsigned j = ksz >> 1; j > 0; j >>= 1) {
#pragma unroll 4
            for (int r = 0; r < 8; r++) {
                const int i = t + r * 1024;
                const int p = i ^ (int)j;
                if (p > i) {
                    const unsigned a = skey[i], c = skey[p];
                    const bool up = ((i & (int)ksz) == 0);
                    if (up ? (a > c) : (a < c)) { skey[i] = c; skey[p] = a; }
                }
            }
            __syncthreads();
        }
    }

    // ---- phase C: gather owned points, bounding sphere ----
    ull pxp[4], pyp[4], pzp[4];
    unsigned oidxp[4];           // two u16 original indices per reg
    float cx_, cy_, cz_, rad;
    {
        float px[8], py[8], pz[8];
#pragma unroll
        for (int p = 0; p < 8; p++) {
            const unsigned oi = skey[8 * t + p] & 8191u;
            px[p] = xb[3 * oi];
            py[p] = xb[3 * oi + 1];
            pz[p] = xb[3 * oi + 2];
            if (p & 1) oidxp[p >> 1] |= oi << 16;
            else       oidxp[p >> 1]  = oi;
        }
#pragma unroll
        for (int i = 0; i < 4; i++) {
            pxp[i] = f2pack(px[2 * i], px[2 * i + 1]);
            pyp[i] = f2pack(py[2 * i], py[2 * i + 1]);
            pzp[i] = f2pack(pz[2 * i], pz[2 * i + 1]);
        }
        float mnx = px[0], mxx = px[0], mny = py[0], mxy = py[0], mnz = pz[0], mxz = pz[0];
#pragma unroll
        for (int p = 1; p < 8; p++) {
            mnx = fminf(mnx, px[p]); mxx = fmaxf(mxx, px[p]);
            mny = fminf(mny, py[p]); mxy = fmaxf(mxy, py[p]);
            mnz = fminf(mnz, pz[p]); mxz = fmaxf(mxz, pz[p]);
        }
        cx_ = 0.5f * (mnx + mxx); cy_ = 0.5f * (mny + mxy); cz_ = 0.5f * (mnz + mxz);
        float r2 = 0.0f;
#pragma unroll
        for (int p = 0; p < 8; p++) {
            const float dx = px[p] - cx_, dy = py[p] - cy_, dz = pz[p] - cz_;
            float d = dx * dx; d = fmaf(dy, dy, d); d = fmaf(dz, dz, d);
            r2 = fmaxf(r2, d);
        }
        rad = sqrtf(r2) * 1.001f + 1e-5f;   // inflated: covers fp error in bound
    }

    // ---- phase D: init distances to original point 0 ----
    float mind[8];
    float bv;
    int candc;                    // cached min original idx among {mind==bv}
    {
        const float qx = xb[0], qy = xb[1], qz = xb[2];
        const ull nqx = f2pack(-qx, -qx), nqy = f2pack(-qy, -qy), nqz = f2pack(-qz, -qz);
        float g[4];
#pragma unroll
        for (int i = 0; i < 4; i++) {
            ull dx = f2add(pxp[i], nqx);
            ull dy = f2add(pyp[i], nqy);
            ull dz = f2add(pzp[i], nqz);
            ull d = f2mul(dx, dx); d = f2fma(dy, dy, d); d = f2fma(dz, dz, d);
            const float2 dd = f2unpack(d);
            mind[2 * i]     = dd.x;
            mind[2 * i + 1] = dd.y;
            g[i] = fmaxf(dd.x, dd.y);
        }
        bv = fmaxf(fmaxf(g[0], g[1]), fmaxf(g[2], g[3]));
        const unsigned bvb = __float_as_uint(bv);
        candc = 0x7fffffff;
#pragma unroll
        for (int p = 0; p < 8; p++)
            if (__float_as_uint(mind[p]) == bvb) {
                const int oi = (int)((oidxp[p >> 1] >> ((p & 1) * 16)) & 0xffffu);
                candc = min(candc, oi);
            }
    }
    if (t == 0) g_fidx[b * NPc] = 0;
    // init all atomic-min slots before the loop
    if (t < 32) {
        si[0][t] = 0x7fffffff; si[1][t] = 0x7fffffff; si[2][t] = 0x7fffffff;
    }
    __syncthreads();

    // cached squared prune threshold: ((rad + sqrt(bv)) * 1.0005)^2
    float sthr2;
    {
        const float s = (rad + sqrtf(bv)) * 1.0005f;
        sthr2 = s * s;
    }

    // ---- phase E: main loop ----
    int s = 1;  // slot for k=1; cycles 1,2,0,1,...
    for (int k = 1; k < NPc; k++) {
        // stage 1: REDUX.MAX, then matching lanes atomicMin their cached candc
        // into this warp's own slot (no cross-warp contention).
        const unsigned bvb = __float_as_uint(bv);
        const unsigned best = __reduce_max_sync(0xffffffffu, bvb);
        int s1 = s + 1; if (s1 >= 3) s1 -= 3;
        if (lane == 0) {
            sv[s][wid] = best;
            si[s1][wid] = 0x7fffffff;   // reset slot used at k+1 (race-free)
        }
        if (bvb == best) atomicMin(&si[s][wid], candc);
        __syncthreads();

        // stage 2: all warps redundantly reduce the 32 (value, index) pairs
        const unsigned wv = sv[s][lane];
        const int      wi = si[s][lane];
        const unsigned gbest = __reduce_max_sync(0xffffffffu, wv);
        const int gcand = (wv == gbest) ? wi : 0x7fffffff;
        const int w = __reduce_min_sync(0xffffffffu, gcand);
        if (t == 0) g_fidx[b * NPc + k] = w;
        s = s1;

        // broadcast load of winner coords (L1-resident, same-address broadcast)
        const float qx = xb[w * 3], qy = xb[w * 3 + 1], qz = xb[w * 3 + 2];

        // exact prune via cached squared threshold
        const float ex = cx_ - qx, ey = cy_ - qy, ez = cz_ - qz;
        float dqc2 = ex * ex; dqc2 = fmaf(ey, ey, dqc2); dqc2 = fmaf(ez, ez, dqc2);
        if (dqc2 < sthr2) {
            const ull nqx = f2pack(-qx, -qx), nqy = f2pack(-qy, -qy), nqz = f2pack(-qz, -qz);
            float g[4];
#pragma unroll
            for (int i = 0; i < 4; i++) {
                ull dx = f2add(pxp[i], nqx);
                ull dy = f2add(pyp[i], nqy);
                ull dz = f2add(pzp[i], nqz);
                ull d = f2mul(dx, dx); d = f2fma(dy, dy, d); d = f2fma(dz, dz, d);
                const float2 dd = f2unpack(d);
                const float m0 = fminf(mind[2 * i],     dd.x);
                const float m1 = fminf(mind[2 * i + 1], dd.y);
                mind[2 * i]     = m0;
                mind[2 * i + 1] = m1;
                g[i] = fmaxf(m0, m1);
            }
            bv = fmaxf(fmaxf(g[0], g[1]), fmaxf(g[2], g[3]));
            // recompute caches (hidden under next iteration's REDUX latency)
            const unsigned nb = __float_as_uint(bv);
            int cc = 0x7fffffff;
#pragma unroll
            for (int p = 0; p < 8; p++)
                if (__float_as_uint(mind[p]) == nb) {
                    const int oi = (int)((oidxp[p >> 1] >> ((p & 1) * 16)) & 0xffffu);
                    cc = min(cc, oi);
                }
            candc = cc;
            const float sn = (rad + sqrtf(bv)) * 1.0005f;
            sthr2 = sn * sn;
        }
    }
}

// ---------------------------------------------------------------------------
// 2) Transpose feats [B, CIN, N] -> featsT [B, N, CIN] for coalesced gathers
// ---------------------------------------------------------------------------
__global__ void __launch_bounds__(256) transpose_kernel(const float* __restrict__ feats) {
    __shared__ float tile[32][33];
    const int b  = blockIdx.z;
    const int n0 = blockIdx.x * 32;
    const int c0 = blockIdx.y * 32;
    const int x = threadIdx.x, y = threadIdx.y;
#pragma unroll
    for (int r = 0; r < 32; r += 8)
        tile[y + r][x] = feats[(size_t)(b * CINc + c0 + y + r) * Nc + n0 + x];
    __syncthreads();
#pragma unroll
    for (int r = 0; r < 32; r += 8)
        g_featsT[(size_t)(b * Nc + n0 + y + r) * CINc + c0 + x] = tile[x][y + r];
}

// ---------------------------------------------------------------------------
// 3) Ball query (warp 0, ballot-compaction with early exit) + gather + maxpool
//    (128 channel-threads). One block per query point.
// ---------------------------------------------------------------------------
__global__ void __launch_bounds__(128) pool_kernel(const float* __restrict__ xyz) {
    const int b = blockIdx.x >> 11;     // / NPc
    const int j = blockIdx.x & (NPc - 1);
    __shared__ int sidx[NSc];
    const int tid = threadIdx.x;

    if (tid < 32) {
        const float* xb = xyz + (size_t)b * Nc * 3;
        const int fi = g_fidx[b * NPc + j];
        const float qx = xb[fi * 3], qy = xb[fi * 3 + 1], qz = xb[fi * 3 + 2];
        const float R2 = 0.04f;  // float(0.04): matches JAX weak-typed 0.2*0.2 promotion
        int count = 0;
        for (int base = 0; base < Nc && count < NSc; base += 32) {
            const int i = base + tid;
            float dx = xb[i * 3] - qx, dy = xb[i * 3 + 1] - qy, dz = xb[i * 3 + 2] - qz;
            float d = dx * dx; d = fmaf(dy, dy, d); d = fmaf(dz, dz, d);
            const bool in = d < R2;
            const unsigned m = __ballot_sync(0xffffffffu, in);
            const int pos = count + __popc(m & ((1u << tid) - 1u));
            if (in && pos < NSc) sidx[pos] = i;
            count += __popc(m);
        }
        __syncwarp();
        // pad with first neighbor (count >= 1 always: query pt is in its own ball)
        const int first = (count > 0) ? sidx[0] : 0;
        for (int s = count + tid; s < NSc; s += 32) sidx[s] = first;
    }
    __syncthreads();

    const float* ft = g_featsT + (size_t)b * Nc * CINc;
    const int c = tid;  // 128 threads == CIN channels
    float m = __int_as_float(0xff800000);  // -inf
#pragma unroll
    for (int s = 0; s < NSc; s++)
        m = fmaxf(m, ft[(size_t)sidx[s] * CINc + c]);
    g_pooledT[((size_t)(b * NPc + j)) * CINc + c] = m;
}

// ---------------------------------------------------------------------------
// 4) out[b,o,j] = lrelu( (W[o,:] . pooledT[b,j,:]) * inv[o] + (beta - rmean*inv)[o] )
//    64x64 shared-tiled SIMT GEMM, 4x4 per-thread microtile, float4 stores.
// ---------------------------------------------------------------------------
__global__ void __launch_bounds__(256) gemm_bn_relu_kernel(
    const float* __restrict__ W,
    const float* __restrict__ gamma, const float* __restrict__ beta,
    const float* __restrict__ rmean, const float* __restrict__ rvar,
    float* __restrict__ out)
{
    __shared__ float Ws[64][33];
    __shared__ float Ps[64][33];
    const int b  = blockIdx.z;
    const int j0 = blockIdx.x * 64;
    const int o0 = blockIdx.y * 64;
    const int tid = threadIdx.x;
    const int tx = tid & 15, ty = tid >> 4;

    const float* Pbase = g_pooledT + ((size_t)b * NPc + j0) * CINc;

    float acc[4][4];
#pragma unroll
    for (int i = 0; i < 4; i++)
#pragma unroll
        for (int jj = 0; jj < 4; jj++) acc[i][jj] = 0.0f;

    for (int k0 = 0; k0 < CINc; k0 += 32) {
#pragma unroll
        for (int l = 0; l < 8; l++) {
            const int idx = tid + l * 256;
            const int r = idx >> 5, kk = idx & 31;
            Ws[r][kk] = W[(size_t)(o0 + r) * CINc + k0 + kk];
            Ps[r][kk] = Pbase[(size_t)r * CINc + k0 + kk];
        }
        __syncthreads();
#pragma unroll
        for (int k = 0; k < 32; k++) {
            const float a0 = Ws[ty * 4 + 0][k], a1 = Ws[ty * 4 + 1][k];
            const float a2 = Ws[ty * 4 + 2][k], a3 = Ws[ty * 4 + 3][k];
            const float p0 = Ps[tx * 4 + 0][k], p1 = Ps[tx * 4 + 1][k];
            const float p2 = Ps[tx * 4 + 2][k], p3 = Ps[tx * 4 + 3][k];
            acc[0][0] += a0 * p0; acc[0][1] += a0 * p1; acc[0][2] += a0 * p2; acc[0][3] += a0 * p3;
            acc[1][0] += a1 * p0; acc[1][1] += a1 * p1; acc[1][2] += a1 * p2; acc[1][3] += a1 * p3;
            acc[2][0] += a2 * p0; acc[2][1] += a2 * p1; acc[2][2] += a2 * p2; acc[2][3] += a2 * p3;
            acc[3][0] += a3 * p0; acc[3][1] += a3 * p1; acc[3][2] += a3 * p2; acc[3][3] += a3 * p3;
        }
        __syncthreads();
    }

#pragma unroll
    for (int oi = 0; oi < 4; oi++) {
        const int o = o0 + ty * 4 + oi;
        const float inv  = gamma[o] / sqrtf(rvar[o] + 1e-5f);
        const float bias = fmaf(-rmean[o], inv, beta[o]);  // beta - rmean*inv
        float vs[4];
#pragma unroll
        for (int ji = 0; ji < 4; ji++) {
            const float y = fmaf(acc[oi][ji], inv, bias);
            vs[ji] = (y >= 0.0f) ? y : 0.2f * y;
        }
        float4 vv = make_float4(vs[0], vs[1], vs[2], vs[3]);
        *reinterpret_cast<float4*>(out + (size_t)(b * COUTc + o) * NPc + j0 + tx * 4) = vv;
    }
}

// ---------------------------------------------------------------------------
extern "C" void kernel_launch(void* const* d_in, const int* in_sizes, int n_in,
                              void* d_out, int out_size) {
    const float* xyz    = (const float*)d_in[0];
    const float* feats  = (const float*)d_in[1];
    const float* conv_w = (const float*)d_in[2];
    const float* gamma  = (const float*)d_in[3];
    const float* beta   = (const float*)d_in[4];
    const float* rmean  = (const float*)d_in[5];
    const float* rvar   = (const float*)d_in[6];
    float* out = (float*)d_out;

    transpose_kernel<<<dim3(Nc / 32, CINc / 32, Bc), dim3(32, 8)>>>(feats);
    fps_kernel<<<Bc, 1024>>>(xyz);
    pool_kernel<<<Bc * NPc, 128>>>(xyz);
    gemm_bn_relu_kernel<<<dim3(NPc / 64, COUTc / 64, Bc), 256>>>(
        conv_w, gamma, beta, rmean, rvar, out);
}

// round 13
// speedup vs baseline: 1.2357x; 1.2357x over previous
#include <cuda_runtime.h>

#define Bc 4
#define Nc 8192
#define NPc 2048
#define NSc 32
#define CINc 128
#define COUTc 256

// Scratch (no cudaMalloc allowed): device globals
__device__ int   g_fidx[Bc * NPc];
__device__ float g_featsT[(size_t)Bc * Nc * CINc];    // [B, N, CIN]  16 MB
__device__ float g_pooledT[(size_t)Bc * NPc * CINc];  // [B, NP, CIN]  4 MB

// ---------------- packed f32x2 helpers (sm_103a) ----------------
// NOTE: only add/mul/fma exist in f32x2 form; min/max do NOT (ptxas rejects).
typedef unsigned long long ull;

__device__ __forceinline__ ull f2pack(float lo, float hi) {
    ull r; asm("mov.b64 %0, {%1, %2};" : "=l"(r) : "f"(lo), "f"(hi)); return r;
}
__device__ __forceinline__ float2 f2unpack(ull v) {
    float2 f; asm("mov.b64 {%0, %1}, %2;" : "=f"(f.x), "=f"(f.y) : "l"(v)); return f;
}
__device__ __forceinline__ ull f2add(ull a, ull b) {
    ull r; asm("add.rn.f32x2 %0, %1, %2;" : "=l"(r) : "l"(a), "l"(b)); return r;
}
__device__ __forceinline__ ull f2mul(ull a, ull b) {
    ull r; asm("mul.rn.f32x2 %0, %1, %2;" : "=l"(r) : "l"(a), "l"(b)); return r;
}
__device__ __forceinline__ ull f2fma(ull a, ull b, ull c) {
    ull r; asm("fma.rn.f32x2 %0, %1, %2, %3;" : "=l"(r) : "l"(a), "l"(b), "l"(c)); return r;
}

__device__ __forceinline__ unsigned expand6(unsigned v) {  // 6 bits -> every 3rd bit
    v = (v * 0x00010001u) & 0xFF0000FFu;
    v = (v * 0x00000101u) & 0x0F00F00Fu;
    v = (v * 0x00000011u) & 0xC30C30C3u;
    v = (v * 0x00000005u) & 0x49249249u;
    return v;
}

// ---------------------------------------------------------------------------
// 1) Furthest point sampling (R11 structure — confirmed best operating point:
//    512 threads/block, 16 Morton-contiguous points/thread, bitonic-sorted in
//    shared, exact per-thread bounding-sphere pruning; flat, branch-minimal).
//    Reduction per iteration (one __syncthreads):
//      stage 1: REDUX.MAX on value bits; lane 0 does ONE ST.64 initializing
//      this warp's u64 slot to (best<<32 | 0x7fffffff); then lanes with
//      bv==best atomicMin their cached candc into the slot's LOW word.
//      Same-warp shared ops to one address complete in program order, so the
//      ST-then-ATOM needs no separate reset: slots are write-before-use.
//      stage 2: ONE LDS.64 per lane (16 slots), REDUX.MAX on value +
//      REDUX.MIN on matching index.
//    Double-buffered by parity: reader of slot s at iter k finishes before
//    bar(k+1); next writer of slot s (iter k+2) starts after bar(k+1).
//    candc (thread-local min original idx among {mind[p]==bv}) and the squared
//    prune threshold are cached, recomputed only in the update branch.
//    Tie-break = lowest original index, exact.
// ---------------------------------------------------------------------------
__global__ void __launch_bounds__(512, 1) fps_kernel(const float* __restrict__ xyz) {
    const int b = blockIdx.x;
    const float* xb = xyz + (size_t)b * Nc * 3;
    const int t = threadIdx.x;
    const int lane = t & 31;
    const int wid = t >> 5;

    __shared__ unsigned skey[Nc];               // 32 KB: (morton18 << 13) | idx13
    __shared__ __align__(16) ull skeys[2][16];  // per-warp (value<<32 | minidx)

    // ---- phase A: build sort keys ----
#pragma unroll
    for (int r = 0; r < 16; r++) {
        const int i = t + r * 512;
        const float x = xb[3 * i], y = xb[3 * i + 1], z = xb[3 * i + 2];
        unsigned cx = min(63u, (unsigned)(x * 64.0f));
        unsigned cy = min(63u, (unsigned)(y * 64.0f));
        unsigned cz = min(63u, (unsigned)(z * 64.0f));
        const unsigned m = (expand6(cz) << 2) | (expand6(cy) << 1) | expand6(cx);
        skey[i] = (m << 13) | (unsigned)i;
    }
    __syncthreads();

    // ---- phase B: bitonic sort (8192 u32) ----
    for (unsigned ksz = 2; ksz <= (unsigned)Nc; ksz <<= 1) {
        for (unsigned j = ksz >> 1; j > 0; j >>= 1) {
#pragma unroll 4
            for (int r = 0; r < 16; r++) {
                const int i = t + r * 512;
                const int p = i ^ (int)j;
                if (p > i) {
                    const unsigned a = skey[i], c = skey[p];
                    const bool up = ((i & (int)ksz) == 0);
                    if (up ? (a > c) : (a < c)) { skey[i] = c; skey[p] = a; }
                }
            }
            __syncthreads();
        }
    }

    // ---- phase C: gather owned points, bounding sphere ----
    ull pxp[8], pyp[8], pzp[8];
    unsigned oidxp[8];           // two u16 original indices per reg
    float cx_, cy_, cz_, rad;
    {
        float px[16], py[16], pz[16];
#pragma unroll
        for (int p = 0; p < 16; p++) {
            const unsigned oi = skey[16 * t + p] & 8191u;
            px[p] = xb[3 * oi];
            py[p] = xb[3 * oi + 1];
            pz[p] = xb[3 * oi + 2];
            if (p & 1) oidxp[p >> 1] |= oi << 16;
            else       oidxp[p >> 1]  = oi;
        }
#pragma unroll
        for (int i = 0; i < 8; i++) {
            pxp[i] = f2pack(px[2 * i], px[2 * i + 1]);
            pyp[i] = f2pack(py[2 * i], py[2 * i + 1]);
            pzp[i] = f2pack(pz[2 * i], pz[2 * i + 1]);
        }
        float mnx = px[0], mxx = px[0], mny = py[0], mxy = py[0], mnz = pz[0], mxz = pz[0];
#pragma unroll
        for (int p = 1; p < 16; p++) {
            mnx = fminf(mnx, px[p]); mxx = fmaxf(mxx, px[p]);
            mny = fminf(mny, py[p]); mxy = fmaxf(mxy, py[p]);
            mnz = fminf(mnz, pz[p]); mxz = fmaxf(mxz, pz[p]);
        }
        cx_ = 0.5f * (mnx + mxx); cy_ = 0.5f * (mny + mxy); cz_ = 0.5f * (mnz + mxz);
        float r2 = 0.0f;
#pragma unroll
        for (int p = 0; p < 16; p++) {
            const float dx = px[p] - cx_, dy = py[p] - cy_, dz = pz[p] - cz_;
            float d = dx * dx; d = fmaf(dy, dy, d); d = fmaf(dz, dz, d);
            r2 = fmaxf(r2, d);
        }
        rad = sqrtf(r2) * 1.001f + 1e-5f;   // inflated: covers fp error in bound
    }

    // ---- phase D: init distances to original point 0 ----
    float mind[16];
    float bv;
    int candc;                    // cached min original idx among {mind==bv}
    {
        const float qx = xb[0], qy = xb[1], qz = xb[2];
        const ull nqx = f2pack(-qx, -qx), nqy = f2pack(-qy, -qy), nqz = f2pack(-qz, -qz);
        float g[8];
#pragma unroll
        for (int i = 0; i < 8; i++) {
            ull dx = f2add(pxp[i], nqx);
            ull dy = f2add(pyp[i], nqy);
            ull dz = f2add(pzp[i], nqz);
            ull d = f2mul(dx, dx); d = f2fma(dy, dy, d); d = f2fma(dz, dz, d);
            const float2 dd = f2unpack(d);
            mind[2 * i]     = dd.x;
            mind[2 * i + 1] = dd.y;
            g[i] = fmaxf(dd.x, dd.y);
        }
        const float t0 = fmaxf(fmaxf(g[0], g[1]), fmaxf(g[2], g[3]));
        const float t1 = fmaxf(fmaxf(g[4], g[5]), fmaxf(g[6], g[7]));
        bv = fmaxf(t0, t1);
        const unsigned bvb = __float_as_uint(bv);
        candc = 0x7fffffff;
#pragma unroll
        for (int p = 0; p < 16; p++)
            if (__float_as_uint(mind[p]) == bvb) {
                const int oi = (int)((oidxp[p >> 1] >> ((p & 1) * 16)) & 0xffffu);
                candc = min(candc, oi);
            }
    }
    if (t == 0) g_fidx[b * NPc] = 0;
    __syncthreads();

    // cached squared prune threshold: ((rad + sqrt(bv)) * 1.0005)^2
    float sthr2;
    {
        const float s = (rad + sqrtf(bv)) * 1.0005f;
        sthr2 = s * s;
    }

    // ---- phase E: main loop ----
    for (int k = 1; k < NPc; k++) {
        const int s = k & 1;
        // stage 1: REDUX.MAX; lane0 ST.64-inits this warp's slot, then
        // matching lanes atomicMin the low word (same-warp in-order shared
        // ops -> no reset/extra buffering needed; write-before-use).
        const unsigned bvb = __float_as_uint(bv);
        const unsigned best = __reduce_max_sync(0xffffffffu, bvb);
        if (lane == 0) skeys[s][wid] = ((ull)best << 32) | 0x7fffffffull;
        if (bvb == best) atomicMin((int*)&skeys[s][wid], candc);   // low word
        __syncthreads();

        // stage 2: one LDS.64 per lane (16 slots, lanes 16-31 duplicate),
        // then REDUX.MAX on value + REDUX.MIN on matching index.
        const ull kk = skeys[s][lane & 15];
        const unsigned wv = (unsigned)(kk >> 32);
        const int      wi = (int)(unsigned)kk;
        const unsigned gbest = __reduce_max_sync(0xffffffffu, wv);
        const int gcand = (wv == gbest) ? wi : 0x7fffffff;
        const int w = __reduce_min_sync(0xffffffffu, gcand);
        if (t == 0) g_fidx[b * NPc + k] = w;

        // broadcast load of winner coords (L1-resident, same-address broadcast)
        const float qx = xb[w * 3], qy = xb[w * 3 + 1], qz = xb[w * 3 + 2];

        // exact prune via cached squared threshold
        const float ex = cx_ - qx, ey = cy_ - qy, ez = cz_ - qz;
        float dqc2 = ex * ex; dqc2 = fmaf(ey, ey, dqc2); dqc2 = fmaf(ez, ez, dqc2);
        if (dqc2 < sthr2) {
            const ull nqx = f2pack(-qx, -qx), nqy = f2pack(-qy, -qy), nqz = f2pack(-qz, -qz);
            float g[8];
#pragma unroll
            for (int i = 0; i < 8; i++) {
                ull dx = f2add(pxp[i], nqx);
                ull dy = f2add(pyp[i], nqy);
                ull dz = f2add(pzp[i], nqz);
                ull d = f2mul(dx, dx); d = f2fma(dy, dy, d); d = f2fma(dz, dz, d);
                const float2 dd = f2unpack(d);
                const float m0 = fminf(mind[2 * i],     dd.x);
                const float m1 = fminf(mind[2 * i + 1], dd.y);
                mind[2 * i]     = m0;
                mind[2 * i + 1] = m1;
                g[i] = fmaxf(m0, m1);
            }
            const float t0 = fmaxf(fmaxf(g[0], g[1]), fmaxf(g[2], g[3]));
            const float t1 = fmaxf(fmaxf(g[4], g[5]), fmaxf(g[6], g[7]));
            bv = fmaxf(t0, t1);
            // recompute caches (hidden under next iteration's REDUX latency)
            const unsigned nb = __float_as_uint(bv);
            int cc = 0x7fffffff;
#pragma unroll
            for (int p = 0; p < 16; p++)
                if (__float_as_uint(mind[p]) == nb) {
                    const int oi = (int)((oidxp[p >> 1] >> ((p & 1) * 16)) & 0xffffu);
                    cc = min(cc, oi);
                }
            candc = cc;
            const float sn = (rad + sqrtf(bv)) * 1.0005f;
            sthr2 = sn * sn;
        }
    }
}

// ---------------------------------------------------------------------------
// 2) Transpose feats [B, CIN, N] -> featsT [B, N, CIN] for coalesced gathers
// ---------------------------------------------------------------------------
__global__ void __launch_bounds__(256) transpose_kernel(const float* __restrict__ feats) {
    __shared__ float tile[32][33];
    const int b  = blockIdx.z;
    const int n0 = blockIdx.x * 32;
    const int c0 = blockIdx.y * 32;
    const int x = threadIdx.x, y = threadIdx.y;
#pragma unroll
    for (int r = 0; r < 32; r += 8)
        tile[y + r][x] = feats[(size_t)(b * CINc + c0 + y + r) * Nc + n0 + x];
    __syncthreads();
#pragma unroll
    for (int r = 0; r < 32; r += 8)
        g_featsT[(size_t)(b * Nc + n0 + y + r) * CINc + c0 + x] = tile[x][y + r];
}

// ---------------------------------------------------------------------------
// 3) Ball query (warp 0, ballot-compaction with early exit) + gather + maxpool
//    (128 channel-threads). One block per query point.
// ---------------------------------------------------------------------------
__global__ void __launch_bounds__(128) pool_kernel(const float* __restrict__ xyz) {
    const int b = blockIdx.x >> 11;     // / NPc
    const int j = blockIdx.x & (NPc - 1);
    __shared__ int sidx[NSc];
    const int tid = threadIdx.x;

    if (tid < 32) {
        const float* xb = xyz + (size_t)b * Nc * 3;
        const int fi = g_fidx[b * NPc + j];
        const float qx = xb[fi * 3], qy = xb[fi * 3 + 1], qz = xb[fi * 3 + 2];
        const float R2 = 0.04f;  // float(0.04): matches JAX weak-typed 0.2*0.2 promotion
        int count = 0;
        for (int base = 0; base < Nc && count < NSc; base += 32) {
            const int i = base + tid;
            float dx = xb[i * 3] - qx, dy = xb[i * 3 + 1] - qy, dz = xb[i * 3 + 2] - qz;
            float d = dx * dx; d = fmaf(dy, dy, d); d = fmaf(dz, dz, d);
            const bool in = d < R2;
            const unsigned m = __ballot_sync(0xffffffffu, in);
            const int pos = count + __popc(m & ((1u << tid) - 1u));
            if (in && pos < NSc) sidx[pos] = i;
            count += __popc(m);
        }
        __syncwarp();
        // pad with first neighbor (count >= 1 always: query pt is in its own ball)
        const int first = (count > 0) ? sidx[0] : 0;
        for (int s = count + tid; s < NSc; s += 32) sidx[s] = first;
    }
    __syncthreads();

    const float* ft = g_featsT + (size_t)b * Nc * CINc;
    const int c = tid;  // 128 threads == CIN channels
    float m = __int_as_float(0xff800000);  // -inf
#pragma unroll
    for (int s = 0; s < NSc; s++)
        m = fmaxf(m, ft[(size_t)sidx[s] * CINc + c]);
    g_pooledT[((size_t)(b * NPc + j)) * CINc + c] = m;
}

// ---------------------------------------------------------------------------
// 4) out[b,o,j] = lrelu( (W[o,:] . pooledT[b,j,:]) * inv[o] + (beta - rmean*inv)[o] )
//    64x64 shared-tiled SIMT GEMM, 4x4 per-thread microtile, float4 stores.
// ---------------------------------------------------------------------------
__global__ void __launch_bounds__(256) gemm_bn_relu_kernel(
    const float* __restrict__ W,
    const float* __restrict__ gamma, const float* __restrict__ beta,
    const float* __restrict__ rmean, const float* __restrict__ rvar,
    float* __restrict__ out)
{
    __shared__ float Ws[64][33];
    __shared__ float Ps[64][33];
    const int b  = blockIdx.z;
    const int j0 = blockIdx.x * 64;
    const int o0 = blockIdx.y * 64;
    const int tid = threadIdx.x;
    const int tx = tid & 15, ty = tid >> 4;

    const float* Pbase = g_pooledT + ((size_t)b * NPc + j0) * CINc;

    float acc[4][4];
#pragma unroll
    for (int i = 0; i < 4; i++)
#pragma unroll
        for (int jj = 0; jj < 4; jj++) acc[i][jj] = 0.0f;

    for (int k0 = 0; k0 < CINc; k0 += 32) {
#pragma unroll
        for (int l = 0; l < 8; l++) {
            const int idx = tid + l * 256;
            const int r = idx >> 5, kk = idx & 31;
            Ws[r][kk] = W[(size_t)(o0 + r) * CINc + k0 + kk];
            Ps[r][kk] = Pbase[(size_t)r * CINc + k0 + kk];
        }
        __syncthreads();
#pragma unroll
        for (int k = 0; k < 32; k++) {
            const float a0 = Ws[ty * 4 + 0][k], a1 = Ws[ty * 4 + 1][k];
            const float a2 = Ws[ty * 4 + 2][k], a3 = Ws[ty * 4 + 3][k];
            const float p0 = Ps[tx * 4 + 0][k], p1 = Ps[tx * 4 + 1][k];
            const float p2 = Ps[tx * 4 + 2][k], p3 = Ps[tx * 4 + 3][k];
            acc[0][0] += a0 * p0; acc[0][1] += a0 * p1; acc[0][2] += a0 * p2; acc[0][3] += a0 * p3;
            acc[1][0] += a1 * p0; acc[1][1] += a1 * p1; acc[1][2] += a1 * p2; acc[1][3] += a1 * p3;
            acc[2][0] += a2 * p0; acc[2][1] += a2 * p1; acc[2][2] += a2 * p2; acc[2][3] += a2 * p3;
            acc[3][0] += a3 * p0; acc[3][1] += a3 * p1; acc[3][2] += a3 * p2; acc[3][3] += a3 * p3;
        }
        __syncthreads();
    }

#pragma unroll
    for (int oi = 0; oi < 4; oi++) {
        const int o = o0 + ty * 4 + oi;
        const float inv  = gamma[o] / sqrtf(rvar[o] + 1e-5f);
        const float bias = fmaf(-rmean[o], inv, beta[o]);  // beta - rmean*inv
        float vs[4];
#pragma unroll
        for (int ji = 0; ji < 4; ji++) {
            const float y = fmaf(acc[oi][ji], inv, bias);
            vs[ji] = (y >= 0.0f) ? y : 0.2f * y;
        }
        float4 vv = make_float4(vs[0], vs[1], vs[2], vs[3]);
        *reinterpret_cast<float4*>(out + (size_t)(b * COUTc + o) * NPc + j0 + tx * 4) = vv;
    }
}

// ---------------------------------------------------------------------------
extern "C" void kernel_launch(void* const* d_in, const int* in_sizes, int n_in,
                              void* d_out, int out_size) {
    const float* xyz    = (const float*)d_in[0];
    const float* feats  = (const float*)d_in[1];
    const float* conv_w = (const float*)d_in[2];
    const float* gamma  = (const float*)d_in[3];
    const float* beta   = (const float*)d_in[4];
    const float* rmean  = (const float*)d_in[5];
    const float* rvar   = (const float*)d_in[6];
    float* out = (float*)d_out;

    transpose_kernel<<<dim3(Nc / 32, CINc / 32, Bc), dim3(32, 8)>>>(feats);
    fps_kernel<<<Bc, 512>>>(xyz);
    pool_kernel<<<Bc * NPc, 128>>>(xyz);
    gemm_bn_relu_kernel<<<dim3(NPc / 64, COUTc / 64, Bc), 256>>>(
        conv_w, gamma, beta, rmean, rvar, out);
}